// round 3
// baseline (speedup 1.0000x reference)
#include <cuda_runtime.h>

namespace {

constexpr int Bsz = 32768;
constexpr int NIN = 41;
constexpr int WPB = 8;   // warps (batch elements) per block
constexpr unsigned FULL = 0xffffffffu;

__device__ __forceinline__ float clamp1(float w) {
    return fminf(fmaxf(w, -1.f), 1.f);
}
__device__ __forceinline__ float clipv(float w) {
    return fminf(fmaxf(w, -0.2f), 1.0f);
}
__device__ __forceinline__ float blurcoef(int x, int y) {
    int d = x - y; if (d < 0) d = -d;
    return (d == 0) ? 0.8f : (d == 1 ? 0.1f : 0.f);
}

__global__ __launch_bounds__(WPB * 32, 3) void pgnet_kernel(
    const float* __restrict__ inp,
    const float* __restrict__ fpg_w,
    const float* __restrict__ fpg_b,
    const float* __restrict__ rpg_w,
    const float* __restrict__ rpg_b,
    const float* __restrict__ pgctrl_w,
    const float* __restrict__ pgctrl_b,
    float* __restrict__ out)
{
    __shared__ float s_wsum[8 * NIN];      // Wc[r,i] + Wc[r,45+i]
    __shared__ float s_wc2[8 * 44];        // Wc[r,45+o], zero-padded
    __shared__ float s_pb[8];
    __shared__ float s_B3[8][9];           // rc blur^3 (8x8, row-padded)
    __shared__ float s_B2[4][4];           // l2 blur^2
    __shared__ float s_inp[WPB][44];
    __shared__ float s_rb[WPB][44];
    __shared__ float4 s_fpg[WPB][328];     // fpg_w[b], natural layout

    const int tid  = threadIdx.x;
    const int warp = tid >> 5;
    const int lane = tid & 31;
    const int b = blockIdx.x * WPB + warp;
    const int q = lane >> 3;               // 0..3
    const int j = lane & 7;                // 0..7

    // ---- rpg_w: coalesced float4 loads -> registers (live across iters) ----
    const float4* rw4 = (const float4*)(rpg_w + (long)b * 1312);
    float4 w4[11];
    #pragma unroll
    for (int s = 0; s < 11; s++) {
        int n = s * 32 + lane;
        if (n < 328) w4[s] = rw4[n];
        else         w4[s] = make_float4(0.f, 0.f, 0.f, 0.f);
    }

    // ---- fpg_w: coalesced float4 -> shared (per-warp) ----
    const float4* fw4 = (const float4*)(fpg_w + (long)b * 1312);
    #pragma unroll
    for (int s = 0; s < 11; s++) {
        int n = s * 32 + lane;
        if (n < 328) s_fpg[warp][n] = fw4[n];
    }

    // ---- per-warp vectors ----
    if (lane < NIN)      { s_inp[warp][lane]      = inp[b * NIN + lane];
                           s_rb[warp][lane]       = rpg_b[b * NIN + lane]; }
    if (lane + 32 < NIN) { s_inp[warp][lane + 32] = inp[b * NIN + lane + 32];
                           s_rb[warp][lane + 32]  = rpg_b[b * NIN + lane + 32]; }
    if (lane >= NIN - 32 && lane < 12) s_rb[warp][lane + 32] = 0.f; // pad 41..43

    // ---- block-shared pgctrl preprocessing + blur-power tables ----
    for (int idx = tid; idx < 8 * 44; idx += WPB * 32) {
        int rr = idx / 44, oo = idx % 44;
        s_wc2[idx] = (oo < NIN) ? pgctrl_w[rr * 86 + 45 + oo] : 0.f;
    }
    for (int idx = tid; idx < 8 * NIN; idx += WPB * 32) {
        int rr = idx / NIN, ii = idx % NIN;
        s_wsum[idx] = pgctrl_w[rr * 86 + ii] + pgctrl_w[rr * 86 + 45 + ii];
    }
    if (tid < 8) s_pb[tid] = pgctrl_b[tid];
    if (tid < 64) {   // B3 = blur^3 over 8 (boundary-correct)
        int r0 = tid >> 3, c0 = tid & 7;
        float acc = 0.f;
        #pragma unroll
        for (int k = 0; k < 8; k++)
            #pragma unroll
            for (int m = 0; m < 8; m++)
                acc += blurcoef(r0, k) * blurcoef(k, m) * blurcoef(m, c0);
        s_B3[r0][c0] = acc;
    }
    if (tid >= 64 && tid < 80) {  // B2 = blur^2 over 4
        int t = tid - 64, r0 = t >> 2, c0 = t & 3;
        float acc = 0.f;
        #pragma unroll
        for (int k = 0; k < 4; k++)
            acc += blurcoef(r0, k) * blurcoef(k, c0);
        s_B2[r0][c0] = acc;
    }

    const float fb = fpg_b[b * 4 + q];

    __syncthreads();

    // clamp rpg weights once
    #pragma unroll
    for (int s = 0; s < 11; s++) {
        w4[s].x = clamp1(w4[s].x);
        w4[s].y = clamp1(w4[s].y);
        w4[s].z = clamp1(w4[s].z);
        w4[s].w = clamp1(w4[s].w);
    }

    const float* si = s_inp[warp];
    const float* sf = (const float*)&s_fpg[warp][0];

    // ---- hoisted fpg dot (conflict-free LDS) ----
    float fdot = 0.f;
    #pragma unroll
    for (int k = 0; k < NIN; k++) {
        float w = clamp1(sf[q * 328 + k * 8 + j]);
        fdot = fmaf(w, si[k], fdot);
    }

    // ---- A_j: iteration-invariant rc preactivation ----
    float A = s_pb[j];
    #pragma unroll
    for (int i = 0; i < NIN; i++) A = fmaf(si[i], s_wsum[j * NIN + i], A);

    float l1i[11];
    #pragma unroll
    for (int s = 0; s < 11; s++) l1i[s] = 0.f;
    float rc = 0.f, l2v = 0.f;
    const int rbase = (j & 1) << 2;
    const int l2src = (j >> 1) << 3;

    #pragma unroll
    for (int it = 0; it < 2; it++) {
        // ---- D_j = sum_o l1i[o] * Wc[j,45+o] (zero on iter 0) ----
        float D = 0.f;
        if (it > 0) {
            #pragma unroll
            for (int s = 0; s < 11; s++)
                D = fmaf(l1i[s], s_wc2[j * 44 + 4 * s + q], D);
            D += __shfl_xor_sync(FULL, D, 8);
            D += __shfl_xor_sync(FULL, D, 16);
        }

        // pre-blur rc value
        float x = A - D;
        x = (x >= 0.f) ? x : 0.2f * x;
        float v = clipv(0.4f * x);

        // gather all 8 pre-blur values once
        float vv[8];
        #pragma unroll
        for (int k = 0; k < 8; k++)
            vv[k] = __shfl_sync(FULL, v, (lane & 24) | k);

        // own rc row (blur^3 as dense matvec)
        {
            float acc = 0.f;
            #pragma unroll
            for (int m = 0; m < 8; m++) acc = fmaf(s_B3[j][m], vv[m], acc);
            rc = acc;
        }
        // the 4 rc values this lane's gate products need: rows rbase..rbase+3
        float rcp[4];
        #pragma unroll
        for (int t = 0; t < 4; t++) {
            float acc = 0.f;
            #pragma unroll
            for (int m = 0; m < 8; m++) acc = fmaf(s_B3[rbase + t][m], vv[m], acc);
            rcp[t] = acc;
        }

        // ---- fpg -> l2: scale + 8-lane reduce + blur^2 (dense) ----
        float acc = fdot * rc;
        acc += __shfl_xor_sync(FULL, acc, 1);
        acc += __shfl_xor_sync(FULL, acc, 2);
        acc += __shfl_xor_sync(FULL, acc, 4);
        float t2 = clipv(0.1f * (acc + fb));
        // gather the 4 q-group values
        float t2a = __shfl_xor_sync(FULL, t2, 8);
        float t2b = __shfl_xor_sync(FULL, t2, 16);
        float t2c = __shfl_xor_sync(FULL, t2, 24);
        float tq[4];
        tq[q] = t2; tq[q ^ 1] = t2a; tq[q ^ 2] = t2b; tq[q ^ 3] = t2c;
        {
            float a2 = 0.f;
            #pragma unroll
            for (int m = 0; m < 4; m++) a2 = fmaf(s_B2[q][m], tq[m], a2);
            l2v = a2;
        }
        // l2 value used by this lane's gate products: row (j>>1)
        float l2i;
        {
            int row = j >> 1;
            float a2 = 0.f;
            #pragma unroll
            for (int m = 0; m < 4; m++) a2 = fmaf(s_B2[row][m], tq[m], a2);
            l2i = a2;
        }

        float p0 = l2i * rcp[0];
        float p1 = l2i * rcp[1];
        float p2 = l2i * rcp[2];
        float p3 = l2i * rcp[3];

        // ---- rpg -> l1i: row o = 4s+q, reduce over j ----
        #pragma unroll
        for (int s = 0; s < 11; s++) {
            float a = w4[s].x * p0;
            a = fmaf(w4[s].y, p1, a);
            a = fmaf(w4[s].z, p2, a);
            a = fmaf(w4[s].w, p3, a);
            a += __shfl_xor_sync(FULL, a, 1);
            a += __shfl_xor_sync(FULL, a, 2);
            a += __shfl_xor_sync(FULL, a, 4);
            l1i[s] = clipv(a + s_rb[warp][4 * s + q]);
        }
    }

    // ---- outputs: concat(l1i [B,41], l2 [B,4], rc [B,8]) ----
    if (j == 0) {
        #pragma unroll
        for (int s = 0; s < 11; s++) {
            int o = 4 * s + q;
            if (o < NIN) out[(long)b * NIN + o] = l1i[s];
        }
        out[(long)Bsz * NIN + b * 4 + q] = l2v;
    }
    if (lane < 8)
        out[(long)Bsz * 45 + b * 8 + lane] = rc;
}

} // namespace

extern "C" void kernel_launch(void* const* d_in, const int* in_sizes, int n_in,
                              void* d_out, int out_size) {
    pgnet_kernel<<<Bsz / WPB, WPB * 32>>>(
        (const float*)d_in[0],   // inp
        (const float*)d_in[1],   // fpg_w
        (const float*)d_in[2],   // fpg_b
        (const float*)d_in[3],   // rpg_w
        (const float*)d_in[4],   // rpg_b
        (const float*)d_in[5],   // pgctrl_w
        (const float*)d_in[6],   // pgctrl_b
        (float*)d_out);
}

// round 5
// speedup vs baseline: 1.0297x; 1.0297x over previous
#include <cuda_runtime.h>
#include <cuda_fp16.h>

namespace {

constexpr int Bsz = 32768;
constexpr int NIN = 41;
constexpr int WPB = 4;   // warps (batch elements) per block
constexpr unsigned FULL = 0xffffffffu;

__device__ __forceinline__ float clamp1(float w) {
    return fminf(fmaxf(w, -1.f), 1.f);
}
__device__ __forceinline__ float clipv(float w) {
    return fminf(fmaxf(w, -0.2f), 1.0f);
}
__device__ __forceinline__ float blurcoef(int x, int y) {
    int d = x - y; if (d < 0) d = -d;
    return (d == 0) ? 0.8f : (d == 1 ? 0.1f : 0.f);
}

__global__ __launch_bounds__(WPB * 32, 6) void pgnet_kernel(
    const float* __restrict__ inp,
    const float* __restrict__ fpg_w,
    const float* __restrict__ fpg_b,
    const float* __restrict__ rpg_w,
    const float* __restrict__ rpg_b,
    const float* __restrict__ pgctrl_w,
    const float* __restrict__ pgctrl_b,
    float* __restrict__ out)
{
    __shared__ float s_wsum[8 * NIN];      // Wc[r,i] + Wc[r,45+i]
    __shared__ float s_wc2[8 * 44];        // Wc[r,45+o], zero-padded
    __shared__ float s_pb[8];
    __shared__ float s_B3[8][9];           // rc blur^3 (8x8, row-padded)
    __shared__ float s_B2[4][4];           // l2 blur^2
    __shared__ float s_inp[WPB][44];
    __shared__ float s_rb[WPB][44];
    __shared__ float4 s_fpg[WPB][328];     // fpg_w[b], natural layout

    const int tid  = threadIdx.x;
    const int warp = tid >> 5;
    const int lane = tid & 31;
    const int b = blockIdx.x * WPB + warp;
    const int q = lane >> 3;               // 0..3
    const int j = lane & 7;                // 0..7

    // ---- rpg_w: coalesced float4 loads -> clamp -> pack half2 (22 regs) ----
    const float4* rw4 = (const float4*)(rpg_w + (long)b * 1312);
    __half2 wh[22];
    #pragma unroll
    for (int s = 0; s < 11; s++) {
        int n = s * 32 + lane;
        float4 f = (n < 328) ? rw4[n] : make_float4(0.f, 0.f, 0.f, 0.f);
        wh[2 * s]     = __floats2half2_rn(clamp1(f.x), clamp1(f.y));
        wh[2 * s + 1] = __floats2half2_rn(clamp1(f.z), clamp1(f.w));
    }

    // ---- fpg_w: coalesced float4 -> shared (per-warp) ----
    const float4* fw4 = (const float4*)(fpg_w + (long)b * 1312);
    #pragma unroll
    for (int s = 0; s < 11; s++) {
        int n = s * 32 + lane;
        if (n < 328) s_fpg[warp][n] = fw4[n];
    }

    // ---- per-warp vectors ----
    if (lane < NIN)      { s_inp[warp][lane]      = inp[b * NIN + lane];
                           s_rb[warp][lane]       = rpg_b[b * NIN + lane]; }
    if (lane + 32 < NIN) { s_inp[warp][lane + 32] = inp[b * NIN + lane + 32];
                           s_rb[warp][lane + 32]  = rpg_b[b * NIN + lane + 32]; }
    if (lane >= 9 && lane < 12) s_rb[warp][lane + 32] = 0.f;  // pad 41..43

    // ---- block-shared pgctrl preprocessing + blur-power tables ----
    for (int idx = tid; idx < 8 * 44; idx += WPB * 32) {
        int rr = idx / 44, oo = idx % 44;
        s_wc2[idx] = (oo < NIN) ? pgctrl_w[rr * 86 + 45 + oo] : 0.f;
    }
    for (int idx = tid; idx < 8 * NIN; idx += WPB * 32) {
        int rr = idx / NIN, ii = idx % NIN;
        s_wsum[idx] = pgctrl_w[rr * 86 + ii] + pgctrl_w[rr * 86 + 45 + ii];
    }
    if (tid < 8) s_pb[tid] = pgctrl_b[tid];
    if (tid < 64) {   // B3 = blur^3 over 8 (boundary-correct)
        int r0 = tid >> 3, c0 = tid & 7;
        float acc = 0.f;
        #pragma unroll
        for (int k = 0; k < 8; k++)
            #pragma unroll
            for (int m = 0; m < 8; m++)
                acc += blurcoef(r0, k) * blurcoef(k, m) * blurcoef(m, c0);
        s_B3[r0][c0] = acc;
    }
    if (tid >= 64 && tid < 80) {  // B2 = blur^2 over 4
        int t = tid - 64, r0 = t >> 2, c0 = t & 3;
        float acc = 0.f;
        #pragma unroll
        for (int k = 0; k < 4; k++)
            acc += blurcoef(r0, k) * blurcoef(k, c0);
        s_B2[r0][c0] = acc;
    }

    const float fb = fpg_b[b * 4 + q];

    __syncthreads();

    const float* si = s_inp[warp];
    const float* sf = (const float*)&s_fpg[warp][0];

    // ---- hoisted fpg dot (conflict-free LDS) ----
    float fdot = 0.f;
    #pragma unroll
    for (int k = 0; k < NIN; k++) {
        float w = clamp1(sf[q * 328 + k * 8 + j]);
        fdot = fmaf(w, si[k], fdot);
    }

    // ---- A_j: iteration-invariant rc preactivation ----
    float A = s_pb[j];
    #pragma unroll
    for (int i = 0; i < NIN; i++) A = fmaf(si[i], s_wsum[j * NIN + i], A);

    float l1i[11];
    #pragma unroll
    for (int s = 0; s < 11; s++) l1i[s] = 0.f;
    float rc = 0.f, l2v = 0.f;
    const int rbase = (j & 1) << 2;

    #pragma unroll
    for (int it = 0; it < 2; it++) {
        // ---- D_j = sum_o l1i[o] * Wc[j,45+o] (zero on iter 0) ----
        float D = 0.f;
        if (it > 0) {
            #pragma unroll
            for (int s = 0; s < 11; s++)
                D = fmaf(l1i[s], s_wc2[j * 44 + 4 * s + q], D);
            D += __shfl_xor_sync(FULL, D, 8);
            D += __shfl_xor_sync(FULL, D, 16);
        }

        // pre-blur rc value
        float x = A - D;
        x = (x >= 0.f) ? x : 0.2f * x;
        float v = clipv(0.4f * x);

        // gather all 8 pre-blur values once (parallel shuffles)
        float vv[8];
        #pragma unroll
        for (int k = 0; k < 8; k++)
            vv[k] = __shfl_sync(FULL, v, (lane & 24) | k);

        // own rc row (blur^3 as dense matvec)
        {
            float acc = 0.f;
            #pragma unroll
            for (int m = 0; m < 8; m++) acc = fmaf(s_B3[j][m], vv[m], acc);
            rc = acc;
        }
        // the 4 rc values this lane's gate products need
        float rcp[4];
        #pragma unroll
        for (int t = 0; t < 4; t++) {
            float acc = 0.f;
            #pragma unroll
            for (int m = 0; m < 8; m++) acc = fmaf(s_B3[rbase + t][m], vv[m], acc);
            rcp[t] = acc;
        }

        // ---- fpg -> l2: scale + 8-lane reduce + blur^2 (dense) ----
        float acc = fdot * rc;
        acc += __shfl_xor_sync(FULL, acc, 1);
        acc += __shfl_xor_sync(FULL, acc, 2);
        acc += __shfl_xor_sync(FULL, acc, 4);
        float t2 = clipv(0.1f * (acc + fb));
        float t2a = __shfl_xor_sync(FULL, t2, 8);
        float t2b = __shfl_xor_sync(FULL, t2, 16);
        float t2c = __shfl_xor_sync(FULL, t2, 24);
        float tq[4];
        tq[q] = t2; tq[q ^ 1] = t2a; tq[q ^ 2] = t2b; tq[q ^ 3] = t2c;
        {
            float a2 = 0.f;
            #pragma unroll
            for (int m = 0; m < 4; m++) a2 = fmaf(s_B2[q][m], tq[m], a2);
            l2v = a2;
        }
        float l2i;
        {
            int row = j >> 1;
            float a2 = 0.f;
            #pragma unroll
            for (int m = 0; m < 4; m++) a2 = fmaf(s_B2[row][m], tq[m], a2);
            l2i = a2;
        }

        float p0 = l2i * rcp[0];
        float p1 = l2i * rcp[1];
        float p2 = l2i * rcp[2];
        float p3 = l2i * rcp[3];

        // ---- rpg -> l1i: row o = 4s+q, reduce over j ----
        #pragma unroll
        for (int s = 0; s < 11; s++) {
            float2 w01 = __half22float2(wh[2 * s]);
            float2 w23 = __half22float2(wh[2 * s + 1]);
            float a = w01.x * p0;
            a = fmaf(w01.y, p1, a);
            a = fmaf(w23.x, p2, a);
            a = fmaf(w23.y, p3, a);
            a += __shfl_xor_sync(FULL, a, 1);
            a += __shfl_xor_sync(FULL, a, 2);
            a += __shfl_xor_sync(FULL, a, 4);
            l1i[s] = clipv(a + s_rb[warp][4 * s + q]);
        }
    }

    // ---- outputs: concat(l1i [B,41], l2 [B,4], rc [B,8]) ----
    if (j == 0) {
        #pragma unroll
        for (int s = 0; s < 11; s++) {
            int o = 4 * s + q;
            if (o < NIN) out[(long)b * NIN + o] = l1i[s];
        }
        out[(long)Bsz * NIN + b * 4 + q] = l2v;
    }
    if (lane < 8)
        out[(long)Bsz * 45 + b * 8 + lane] = rc;
}

} // namespace

extern "C" void kernel_launch(void* const* d_in, const int* in_sizes, int n_in,
                              void* d_out, int out_size) {
    pgnet_kernel<<<Bsz / WPB, WPB * 32>>>(
        (const float*)d_in[0],   // inp
        (const float*)d_in[1],   // fpg_w
        (const float*)d_in[2],   // fpg_b
        (const float*)d_in[3],   // rpg_w
        (const float*)d_in[4],   // rpg_b
        (const float*)d_in[5],   // pgctrl_w
        (const float*)d_in[6],   // pgctrl_b
        (float*)d_out);
}

// round 6
// speedup vs baseline: 1.1281x; 1.0955x over previous
#include <cuda_runtime.h>
#include <cuda_fp16.h>

namespace {

constexpr int Bsz = 32768;
constexpr int NIN = 41;
constexpr int WPB = 4;
constexpr unsigned FULL = 0xffffffffu;

__device__ __forceinline__ float clamp1(float w) {
    return fminf(fmaxf(w, -1.f), 1.f);
}
__device__ __forceinline__ float clipv(float w) {
    return fminf(fmaxf(w, -0.2f), 1.0f);
}
__device__ __forceinline__ float blurcoef(int x, int y) {
    int d = x - y; if (d < 0) d = -d;
    return (d == 0) ? 0.8f : (d == 1 ? 0.1f : 0.f);
}

__global__ __launch_bounds__(WPB * 32, 7) void pgnet_kernel(
    const float* __restrict__ inp,
    const float* __restrict__ fpg_w,
    const float* __restrict__ fpg_b,
    const float* __restrict__ rpg_w,
    const float* __restrict__ rpg_b,
    const float* __restrict__ pgctrl_w,
    const float* __restrict__ pgctrl_b,
    float* __restrict__ out)
{
    __shared__ float s_wsum[8][44];
    __shared__ float s_wc2[8][44];
    __shared__ float s_pb[8];
    __shared__ float s_B3[8][9];
    __shared__ float s_B2[4][5];
    __shared__ float s_inp[WPB][44];
    __shared__ float s_rb[WPB][44];
    // fpg half: half2 idx = o*164 + k*4 + (r>>1); pick half by r&1
    __shared__ __align__(16) __half2 s_fpgh[WPB][656];
    // rpg half, r-transposed: half2 idx = (r>>1)*176 + o*4 + i; pick half by r&1
    __shared__ __align__(16) __half2 s_rpgT[WPB][704];

    const int tid  = threadIdx.x;
    const int warp = tid >> 5;
    const int lane = tid & 31;
    const int b = blockIdx.x * WPB + warp;
    const int q = lane >> 3;               // 0..3
    const int j = lane & 7;                // 0..7

    const float4* rw4 = (const float4*)(rpg_w + (long)b * 1312);
    const float4* fw4 = (const float4*)(fpg_w + (long)b * 1312);

    // ---- stage both weight tensors: coalesced LDG.128 -> clamp -> half2 smem ----
    #pragma unroll
    for (int s = 0; s < 11; s++) {
        int n = s * 32 + lane;
        if (n < 328) {
            // rpg float4 #n = w[o = n/8 = 4s+q, i = j>>1, r = 4*(j&1)+{0..3}]
            float4 f = rw4[n];
            int o = 4 * s + q;
            int i = j >> 1;
            int rp = (j & 1) << 1;
            s_rpgT[warp][rp * 176 + o * 4 + i] =
                __floats2half2_rn(clamp1(f.x), clamp1(f.y));
            s_rpgT[warp][(rp + 1) * 176 + o * 4 + i] =
                __floats2half2_rn(clamp1(f.z), clamp1(f.w));
            // fpg float4 #n = w[o2 = n/82, k = (n%82)>>1, r = 4*(n&1)+{0..3}]
            float4 g = fw4[n];
            int o2 = n / 82;
            int m  = n % 82;
            int base = o2 * 164 + (m >> 1) * 4 + ((m & 1) << 1);
            s_fpgh[warp][base]     = __floats2half2_rn(clamp1(g.x), clamp1(g.y));
            s_fpgh[warp][base + 1] = __floats2half2_rn(clamp1(g.z), clamp1(g.w));
        }
    }
    // zero-fill rpg pad rows o=41..43 (read as zero weights)
    if (lane < 12) {
        #pragma unroll
        for (int rp = 0; rp < 4; rp++)
            s_rpgT[warp][rp * 176 + 164 + lane] = __floats2half2_rn(0.f, 0.f);
    }

    // ---- per-warp vectors ----
    if (lane < NIN)      { s_inp[warp][lane]      = inp[b * NIN + lane];
                           s_rb[warp][lane]       = rpg_b[b * NIN + lane]; }
    if (lane + 32 < NIN) { s_inp[warp][lane + 32] = inp[b * NIN + lane + 32];
                           s_rb[warp][lane + 32]  = rpg_b[b * NIN + lane + 32]; }
    if (lane >= 9 && lane < 12) s_rb[warp][lane + 32] = 0.f;  // pad 41..43

    // ---- block-shared pgctrl tables + blur powers ----
    for (int idx = tid; idx < 8 * 44; idx += WPB * 32) {
        int rr = idx / 44, oo = idx % 44;
        float w2 = (oo < NIN) ? pgctrl_w[rr * 86 + 45 + oo] : 0.f;
        s_wc2[rr][oo]  = w2;
        s_wsum[rr][oo] = (oo < NIN) ? (pgctrl_w[rr * 86 + oo] + w2) : 0.f;
    }
    if (tid < 8) s_pb[tid] = pgctrl_b[tid];
    if (tid < 64) {
        int r0 = tid >> 3, c0 = tid & 7;
        float acc = 0.f;
        #pragma unroll
        for (int k = 0; k < 8; k++)
            #pragma unroll
            for (int m = 0; m < 8; m++)
                acc += blurcoef(r0, k) * blurcoef(k, m) * blurcoef(m, c0);
        s_B3[r0][c0] = acc;
    }
    if (tid >= 64 && tid < 80) {
        int t = tid - 64, r0 = t >> 2, c0 = t & 3;
        float acc = 0.f;
        #pragma unroll
        for (int k = 0; k < 4; k++)
            acc += blurcoef(r0, k) * blurcoef(k, c0);
        s_B2[r0][c0] = acc;
    }

    const float fb = fpg_b[b * 4 + q];
    __syncthreads();

    const float* si = s_inp[warp];
    const bool hi = (j & 1);

    // ---- hoisted fpg dot: fdot(o=q, r=j); dual float2 accumulate ----
    float fax = 0.f, fay = 0.f;
    {
        const __half2* fp = &s_fpgh[warp][q * 164 + (j >> 1)];
        #pragma unroll
        for (int k = 0; k < NIN; k++) {
            float2 w = __half22float2(fp[k * 4]);
            fax = fmaf(w.x, si[k], fax);
            fay = fmaf(w.y, si[k], fay);
        }
    }
    const float fdot = hi ? fay : fax;

    // ---- A_j: iteration-invariant rc preactivation ----
    float A = s_pb[j];
    #pragma unroll
    for (int i = 0; i < NIN; i++) A = fmaf(si[i], s_wsum[j][i], A);

    float l1i[11];
    #pragma unroll
    for (int s = 0; s < 11; s++) l1i[s] = 0.f;
    float rc = 0.f, l2v = 0.f;

    #pragma unroll
    for (int it = 0; it < 2; it++) {
        // ---- D_j = sum_o l1i[o] * Wc[j,45+o] (zero on iter 0) ----
        float D = 0.f;
        if (it > 0) {
            #pragma unroll
            for (int s = 0; s < 11; s++)
                D = fmaf(l1i[s], s_wc2[j][4 * s + q], D);
            D += __shfl_xor_sync(FULL, D, 8);
            D += __shfl_xor_sync(FULL, D, 16);
        }

        // pre-blur rc value
        float x = A - D;
        x = (x >= 0.f) ? x : 0.2f * x;
        float v = clipv(0.4f * x);

        // gather all 8 pre-blur values; own rc row via dense blur^3
        float vv[8];
        #pragma unroll
        for (int k = 0; k < 8; k++)
            vv[k] = __shfl_sync(FULL, v, (lane & 24) | k);
        {
            float acc = 0.f;
            #pragma unroll
            for (int m = 0; m < 8; m++) acc = fmaf(s_B3[j][m], vv[m], acc);
            rc = acc;
        }

        // ---- fpg -> l2: scale + 8-lane reduce + dense blur^2 (all 4 rows) ----
        float acc = fdot * rc;
        acc += __shfl_xor_sync(FULL, acc, 1);
        acc += __shfl_xor_sync(FULL, acc, 2);
        acc += __shfl_xor_sync(FULL, acc, 4);
        float t2 = clipv(0.1f * (acc + fb));
        float t2a = __shfl_xor_sync(FULL, t2, 8);
        float t2b = __shfl_xor_sync(FULL, t2, 16);
        float t2c = __shfl_xor_sync(FULL, t2, 24);
        float tq[4];
        tq[q] = t2; tq[q ^ 1] = t2a; tq[q ^ 2] = t2b; tq[q ^ 3] = t2c;
        float l2all[4];
        #pragma unroll
        for (int i = 0; i < 4; i++) {
            float a2 = 0.f;
            #pragma unroll
            for (int m = 0; m < 4; m++) a2 = fmaf(s_B2[i][m], tq[m], a2);
            l2all[i] = a2;
        }
        l2v = l2all[q];

        // gate products: p_i = l2[i] * rc_own (lane owns r = j)
        float p0 = l2all[0] * rc;
        float p1 = l2all[1] * rc;
        float p2 = l2all[2] * rc;
        float p3 = l2all[3] * rc;

        // ---- rpg -> l1i: lane reads w[o=4s+q, i=0..3, r=j] as one LDS.128 ----
        const __half2* rpp = &s_rpgT[warp][(j >> 1) * 176];
        #pragma unroll
        for (int s = 0; s < 11; s++) {
            float4 rv = *(const float4*)(rpp + (4 * s + q) * 4);
            float2 w0 = __half22float2(*(const __half2*)&rv.x);
            float2 w1 = __half22float2(*(const __half2*)&rv.y);
            float2 w2 = __half22float2(*(const __half2*)&rv.z);
            float2 w3 = __half22float2(*(const __half2*)&rv.w);
            float c0 = hi ? w0.y : w0.x;
            float c1 = hi ? w1.y : w1.x;
            float c2 = hi ? w2.y : w2.x;
            float c3 = hi ? w3.y : w3.x;
            float a = c0 * p0;
            a = fmaf(c1, p1, a);
            a = fmaf(c2, p2, a);
            a = fmaf(c3, p3, a);
            a += __shfl_xor_sync(FULL, a, 1);
            a += __shfl_xor_sync(FULL, a, 2);
            a += __shfl_xor_sync(FULL, a, 4);
            l1i[s] = clipv(a + s_rb[warp][4 * s + q]);
        }
    }

    // ---- outputs: concat(l1i [B,41], l2 [B,4], rc [B,8]) ----
    if (j == 0) {
        #pragma unroll
        for (int s = 0; s < 11; s++) {
            int o = 4 * s + q;
            if (o < NIN) out[(long)b * NIN + o] = l1i[s];
        }
        out[(long)Bsz * NIN + b * 4 + q] = l2v;
    }
    if (lane < 8)
        out[(long)Bsz * 45 + b * 8 + lane] = rc;
}

} // namespace

extern "C" void kernel_launch(void* const* d_in, const int* in_sizes, int n_in,
                              void* d_out, int out_size) {
    pgnet_kernel<<<Bsz / WPB, WPB * 32>>>(
        (const float*)d_in[0],   // inp
        (const float*)d_in[1],   // fpg_w
        (const float*)d_in[2],   // fpg_b
        (const float*)d_in[3],   // rpg_w
        (const float*)d_in[4],   // rpg_b
        (const float*)d_in[5],   // pgctrl_w
        (const float*)d_in[6],   // pgctrl_b
        (float*)d_out);
}